// round 11
// baseline (speedup 1.0000x reference)
#include <cuda_runtime.h>

// LIF: v = alpha*v + beta*c ; s = (v >= 1) ; v reset to 0 where spiked.
// T=2048 sequential steps, N=32768 independent neurons.
//
// Speculative no-reset kernel (spikes are ~6.3-sigma events, P~1e-10): pure
// linear recurrence, spikes written as zeros, per-neuron running max tracked
// in registers; in-thread exact fixup for any neuron that nears threshold.
//
// R9/R10 (resubmit, broker timeouts): 1 neuron/thread (32768 threads, 1024
// warps) instead of 2 packed neurons/thread (512 warps). In-flight bytes
// unchanged (48-deep prefetch, 6.3 MB chip-wide) but 2x the independent
// issue streams per SMSP. R8 profile showed DRAM only 74.3% active with
// issue at 6.9%: demand is bursty (each warp alternates 16-load bursts with
// ~64-cyc serial FMA chains), and with <2 warps/SMSP the memory pipe drains
// during compute phases. More warps smooth the LDG stream -> DRAM ~85%.

#define LIF_T   2048
#define LIF_N   32768
#define LIF_U   16              // steps per batch
#define LIF_NB  (LIF_T / LIF_U) // 128 batches
#define LIF_BLK 128

__device__ __forceinline__ void lif_load(const float*& cp, int& nl,
                                         float (&b)[LIF_U]) {
    if (nl < LIF_NB) {
#pragma unroll
        for (int i = 0; i < LIF_U; i++) b[i] = __ldcs(cp + i * LIF_N);
        cp += LIF_U * LIF_N;
    }
    nl++;
}

__device__ __forceinline__ void lif_compute(const float (&b)[LIF_U],
                                            float& v, float alpha, float beta,
                                            float& m,
                                            float*& sp, float*& vp) {
#pragma unroll
    for (int i = 0; i < LIF_U; i++) {
        // bc off the chain; recurrence chain is one FFMA (lat 4)
        const float bc = __fmul_rn(beta, b[i]);
        v = __fmaf_rn(alpha, v, bc);
        m = fmaxf(m, v);
        __stcs(sp + i * LIF_N, 0.0f);   // speculative spike = 0
        __stcs(vp + i * LIF_N, v);      // no-reset voltage
    }
    sp += LIF_U * LIF_N;
    vp += LIF_U * LIF_N;
}

__global__ __launch_bounds__(LIF_BLK)
void lif_main(const float* __restrict__ currents,
              const float* __restrict__ v0,
              float* __restrict__ out)
{
    const int n = blockIdx.x * LIF_BLK + threadIdx.x;   // 0..32767

    const float alpha = 0.95122942450071400909f;  // f32(exp(-1/20))
    const float beta  = 0.04877057549928599090f;  // f32(1 - exp(-1/20))

    float v = v0[n];
    float m = -3.0e38f;

    const float* cp = currents + n;
    float* sp = out + n;                          // spikes
    float* vp = out + (size_t)LIF_T * LIF_N + n;  // voltages

    float bA[LIF_U], bB[LIF_U], bC[LIF_U], bD[LIF_U];
    int nl = 0;   // next batch index to load

    // Prime 3 batches ahead (48 loads in flight per thread).
    lif_load(cp, nl, bA);
    lif_load(cp, nl, bB);
    lif_load(cp, nl, bC);

    // 128 batches, 4 rotating slots: loads stay 3 batches ahead of compute.
#pragma unroll 1
    for (int it = 0; it < LIF_NB / 4; it++) {
        lif_load(cp, nl, bD);
        lif_compute(bA, v, alpha, beta, m, sp, vp);
        lif_load(cp, nl, bA);
        lif_compute(bB, v, alpha, beta, m, sp, vp);
        lif_load(cp, nl, bB);
        lif_compute(bC, v, alpha, beta, m, sp, vp);
        lif_load(cp, nl, bC);
        lif_compute(bD, v, alpha, beta, m, sp, vp);
    }

    // ---- In-thread fixup (statistically never taken; exact if it is) ----
    // Re-run the exact reference recurrence (unfused mul/add, with reset)
    // and overwrite this neuron's columns. 0.999 margin absorbs
    // fused-vs-unfused drift between speculative and exact trajectories.
    if (m >= 0.999f) {
        float vs = v0[n];
        float* sfp = out + n;
        float* vfp = out + (size_t)LIF_T * LIF_N + n;
#pragma unroll 1
        for (int t = 0; t < LIF_T; t++) {
            const float c = __ldg(currents + (size_t)t * LIF_N + n);
            vs = __fadd_rn(__fmul_rn(alpha, vs), __fmul_rn(beta, c));
            const float s = (vs >= 1.0f) ? 1.0f : 0.0f;
            if (s == 1.0f) vs = 0.0f;          // exact reset
            sfp[(size_t)t * LIF_N] = s;
            vfp[(size_t)t * LIF_N] = vs;
        }
    }
}

extern "C" void kernel_launch(void* const* d_in, const int* in_sizes, int n_in,
                              void* d_out, int out_size)
{
    const float* currents = (const float*)d_in[0];   // (T, N) fp32
    const float* v0       = (const float*)d_in[1];   // (N,)  fp32
    float* out            = (float*)d_out;           // (2, T, N): spikes, voltages

    (void)in_sizes; (void)n_in; (void)out_size;

    lif_main<<<LIF_N / LIF_BLK, LIF_BLK>>>(currents, v0, out);   // 256 blocks x 128
}

// round 15
// speedup vs baseline: 1.0171x; 1.0171x over previous
#include <cuda_runtime.h>

// LIF: v = alpha*v + beta*c ; s = (v >= 1) ; v reset to 0 where spiked.
// T=2048 sequential steps, N=32768 independent neurons.
//
// Speculative no-reset kernel (spikes are ~6.3-sigma events, P~1e-10): pure
// linear recurrence in packed f32x2 (2 neurons/thread, 512 warps), spikes
// written as zeros, per-neuron running max tracked in registers, in-thread
// exact fixup. 4-slot rotating prefetch keeps ~48 LDG.64 in flight/thread.
//
// R12-R15 (resubmit, broker timeouts): single change vs the proven R8 config
// (130.9us) — stores use default write-back st.global instead of .cs
// streaming, letting the 126MB L2 batch dirty write-backs into longer DRAM
// write bursts (fewer read/write turnarounds; DRAM was only 74.3% active
// with in-flight bytes at 2.7x the Little's-law requirement, and R11 ruled
// out warp-count starvation). Reads keep .cs (zero reuse; don't pollute L2).

#define LIF_T   2048
#define LIF_N   32768
#define LIF_S   (LIF_N / 2)     // row stride in float2 units
#define LIF_U   16              // steps per batch
#define LIF_NB  (LIF_T / LIF_U) // 128 batches
#define LIF_BLK 64

__device__ __forceinline__ void lif_load(const unsigned long long*& cp, int& nl,
                                         unsigned long long (&b)[LIF_U]) {
    if (nl < LIF_NB) {
#pragma unroll
        for (int i = 0; i < LIF_U; i++) b[i] = __ldcs(cp + i * LIF_S);
        cp += LIF_U * LIF_S;
    }
    nl++;
}

__device__ __forceinline__ void lif_compute(const unsigned long long (&b)[LIF_U],
                                            unsigned long long& v,
                                            unsigned long long a2,
                                            unsigned long long b2,
                                            float& m0, float& m1,
                                            unsigned long long*& sp,
                                            unsigned long long*& vp) {
#pragma unroll
    for (int i = 0; i < LIF_U; i++) {
        unsigned long long bc, vn;
        // bc = beta * c  (off the sequential dependency chain)
        asm("mul.rn.f32x2 %0, %1, %2;" : "=l"(bc) : "l"(b2), "l"(b[i]));
        // v = alpha * v + bc  (recurrence chain: one packed FFMA, lat 4)
        asm("fma.rn.f32x2 %0, %1, %2, %3;" : "=l"(vn) : "l"(a2), "l"(v), "l"(bc));
        v = vn;
        float lo, hi;
        asm("mov.b64 {%0,%1}, %2;" : "=f"(lo), "=f"(hi) : "l"(v));
        m0 = fmaxf(m0, lo);
        m1 = fmaxf(m1, hi);
        // Default write-back stores (R12 change): L2 batches the dirty
        // evictions into long DRAM write bursts.
        sp[i * LIF_S] = 0ull;   // speculative spike = 0
        vp[i * LIF_S] = v;      // no-reset voltage
    }
    sp += LIF_U * LIF_S;
    vp += LIF_U * LIF_S;
}

__global__ __launch_bounds__(LIF_BLK)
void lif_main(const float* __restrict__ currents,
              const float* __restrict__ v0,
              float* __restrict__ out)
{
    const int tid = blockIdx.x * LIF_BLK + threadIdx.x;   // 0..16383

    const float alpha = 0.95122942450071400909f;  // f32(exp(-1/20))
    const float beta  = 0.04877057549928599090f;  // f32(1 - exp(-1/20))

    unsigned long long a2, b2, v;
    asm("mov.b64 %0, {%1,%1};" : "=l"(a2) : "f"(alpha));
    asm("mov.b64 %0, {%1,%1};" : "=l"(b2) : "f"(beta));
    {
        float v0lo = v0[2 * tid], v0hi = v0[2 * tid + 1];
        asm("mov.b64 %0, {%1,%2};" : "=l"(v) : "f"(v0lo), "f"(v0hi));
    }
    float m0 = -3.0e38f, m1 = -3.0e38f;

    const unsigned long long* cp = (const unsigned long long*)currents + tid;
    unsigned long long* sp = (unsigned long long*)out + tid;                          // spikes
    unsigned long long* vp = (unsigned long long*)out + (size_t)LIF_T * LIF_S + tid;  // voltages

    unsigned long long bA[LIF_U], bB[LIF_U], bC[LIF_U], bD[LIF_U];
    int nl = 0;   // next batch index to load

    // Prime 3 batches ahead (48 loads in flight).
    lif_load(cp, nl, bA);
    lif_load(cp, nl, bB);
    lif_load(cp, nl, bC);

    // 128 batches, 4 rotating slots: loads stay 3 batches ahead of compute.
#pragma unroll 1
    for (int it = 0; it < LIF_NB / 4; it++) {
        lif_load(cp, nl, bD);
        lif_compute(bA, v, a2, b2, m0, m1, sp, vp);
        lif_load(cp, nl, bA);
        lif_compute(bB, v, a2, b2, m0, m1, sp, vp);
        lif_load(cp, nl, bB);
        lif_compute(bC, v, a2, b2, m0, m1, sp, vp);
        lif_load(cp, nl, bC);
        lif_compute(bD, v, a2, b2, m0, m1, sp, vp);
    }

    // ---- In-thread fixup (statistically never taken; exact if it is) ----
    // Re-run the exact reference recurrence (unfused mul/add, with reset)
    // for any neuron whose speculative max neared threshold; overwrite its
    // columns. 0.999 margin absorbs fused-vs-unfused drift.
    if (m0 >= 0.999f || m1 >= 0.999f) {
#pragma unroll 1
        for (int k = 0; k < 2; k++) {
            const float mk = (k == 0) ? m0 : m1;
            if (mk < 0.999f) continue;
            const int n = 2 * tid + k;
            float vs = v0[n];
            float* sfp = out + n;
            float* vfp = out + (size_t)LIF_T * LIF_N + n;
#pragma unroll 1
            for (int t = 0; t < LIF_T; t++) {
                const float c = __ldg(currents + (size_t)t * LIF_N + n);
                vs = __fadd_rn(__fmul_rn(alpha, vs), __fmul_rn(beta, c));
                const float s = (vs >= 1.0f) ? 1.0f : 0.0f;
                if (s == 1.0f) vs = 0.0f;          // exact reset
                sfp[(size_t)t * LIF_N] = s;
                vfp[(size_t)t * LIF_N] = vs;
            }
        }
    }
}

extern "C" void kernel_launch(void* const* d_in, const int* in_sizes, int n_in,
                              void* d_out, int out_size)
{
    const float* currents = (const float*)d_in[0];   // (T, N) fp32
    const float* v0       = (const float*)d_in[1];   // (N,)  fp32
    float* out            = (float*)d_out;           // (2, T, N): spikes, voltages

    (void)in_sizes; (void)n_in; (void)out_size;

    lif_main<<<LIF_S / LIF_BLK, LIF_BLK>>>(currents, v0, out);   // 256 blocks x 64
}